// round 16
// baseline (speedup 1.0000x reference)
#include <cuda_runtime.h>
#include <cuda_bf16.h>
#include <cstdint>

// ---------------- problem constants ----------------
#define B_    8
#define TTXT  40
#define SIMG  1024
#define NTOK  1064
#define CDIM  768
#define H_    12
#define HD    64
#define MROWS (B_*NTOK)       // 8512
#define MPAD  8576            // 67*128
#define KC    (2*CDIM)        // 1536 : compact [hi|lo] K length
#define NQKV  (3*CDIM)        // 2304

// ---------------- device scratch (referenced ONLY from device code) ----------------
__device__ __align__(16) __nv_bfloat16 gxc [MPAD*KC];
__device__ __align__(16) __nv_bfloat16 gw1c[NQKV*KC];
__device__ __align__(16) __nv_bfloat16 gw2c[CDIM*KC];
__device__ __align__(16) __nv_bfloat16 gaoc[MPAD*KC];

__device__ __align__(16) __nv_bfloat16 g_qc [B_*H_*NTOK*128];  // [bh][n][hi64|lo64]
__device__ __align__(16) __nv_bfloat16 g_kc [B_*H_*NTOK*128];  // [bh][n][hi64|lo64]
__device__ __align__(16) __nv_bfloat16 g_vht[B_*H_*HD*NTOK];   // V^T hi: [bh][e][n]
__device__ __align__(16) __nv_bfloat16 g_vlt[B_*H_*HD*NTOK];   // V^T lo

// ---------------- helpers ----------------
__device__ __forceinline__ void pack_hilo(float x, float y, uint32_t& hi, uint32_t& lo)
{
    __nv_bfloat162 h = __floats2bfloat162_rn(x, y);
    float hx = __bfloat162float(h.x), hy = __bfloat162float(h.y);
    __nv_bfloat162 l = __floats2bfloat162_rn(x - hx, y - hy);
    hi = *(uint32_t*)&h;
    lo = *(uint32_t*)&l;
}

// ---------------- split kernels ----------------
__global__ __launch_bounds__(256) void split_x_kernel(const float* __restrict__ src)
{
    int i = blockIdx.x * 256 + threadIdx.x;
    if (i >= MPAD * (CDIM/2)) return;
    int row = i / (CDIM/2), c = (i - row * (CDIM/2)) * 2;
    float f0 = 0.f, f1 = 0.f;
    if (row < MROWS) {
        float2 v = *(const float2*)(src + (size_t)row * CDIM + c);
        f0 = v.x; f1 = v.y;
    }
    uint32_t hp, lp;
    pack_hilo(f0, f1, hp, lp);
    *(uint32_t*)(gxc + (size_t)row * KC + c)       = hp;
    *(uint32_t*)(gxc + (size_t)row * KC + 768 + c) = lp;
}

__global__ __launch_bounds__(256) void split_w_kernel(const float* __restrict__ w1,
                                                      const float* __restrict__ w2)
{
    int i = blockIdx.x * 256 + threadIdx.x;
    if (i >= (NQKV + CDIM) * (CDIM/2)) return;
    int row = i / (CDIM/2), c = (i - row * (CDIM/2)) * 2;
    const float* src;
    __nv_bfloat16* dst;
    int r;
    if (row < NQKV) { src = w1; dst = gw1c; r = row; }
    else            { src = w2; dst = gw2c; r = row - NQKV; }
    float2 v = *(const float2*)(src + (size_t)r * CDIM + c);
    uint32_t hp, lp;
    pack_hilo(v.x, v.y, hp, lp);
    *(uint32_t*)(dst + (size_t)r * KC + c)       = hp;
    *(uint32_t*)(dst + (size_t)r * KC + 768 + c) = lp;
}

// ---------------- warp mma + ldmatrix + cp.async ----------------
__device__ __forceinline__ void mma16816(float* d, const uint32_t* a, const uint32_t* b)
{
    asm volatile(
        "mma.sync.aligned.m16n8k16.row.col.f32.bf16.bf16.f32 "
        "{%0,%1,%2,%3}, {%4,%5,%6,%7}, {%8,%9}, {%0,%1,%2,%3};"
        : "+f"(d[0]), "+f"(d[1]), "+f"(d[2]), "+f"(d[3])
        : "r"(a[0]), "r"(a[1]), "r"(a[2]), "r"(a[3]), "r"(b[0]), "r"(b[1]));
}

__device__ __forceinline__ void ldsm4(uint32_t* r, uint32_t addr)
{
    asm volatile("ldmatrix.sync.aligned.m8n8.x4.shared.b16 {%0,%1,%2,%3}, [%4];"
        : "=r"(r[0]), "=r"(r[1]), "=r"(r[2]), "=r"(r[3]) : "r"(addr));
}

__device__ __forceinline__ void cpa16(uint32_t dst, const void* src)
{
    asm volatile("cp.async.cg.shared.global [%0], [%1], 16;" :: "r"(dst), "l"(src));
}
#define CP_COMMIT() asm volatile("cp.async.commit_group;" ::: "memory")
#define CP_WAIT(n)  asm volatile("cp.async.wait_group %0;" :: "n"(n) : "memory")

// D[128,128], 3-term split GEMM, term-grouped (round-14 validated).
#define CSTG  10240
#define GSTG  (4*CSTG)
#define GEMM_SMEM (2*GSTG)           // 81920

__device__ __forceinline__ void gemm_main(const __nv_bfloat16* __restrict__ A,
                                          const __nv_bfloat16* __restrict__ B,
                                          int m0, int n0, float acc[4][8][4],
                                          char* gsm)
{
    const int tid  = threadIdx.x;
    const int lane = tid & 31, wid = tid >> 5;
    const int wm = (wid & 1) * 64;
    const int wn = (wid >> 1) * 64;

    const int lr = tid >> 2;
    const int lkb = (tid & 3) * 16;

    const uint32_t sm0 = (uint32_t)__cvta_generic_to_shared(gsm);

    const char* Ap = (const char*)(A + (size_t)(m0 + lr) * KC) + lkb;
    const char* Bp = (const char*)(B + (size_t)(n0 + lr) * KC) + lkb;

    const uint32_t d0 = sm0 + lr * 80 + lkb;

    const uint32_t aOff = ((wm + (lane & 15)) * 80 + (lane >> 4) * 16);
    const uint32_t bOff = ((wn + ((lane >> 4) * 8) + (lane & 7)) * 80
                           + ((lane >> 3) & 1) * 16);

    const int NKI = 24;

    auto load_chunk = [&](int c, int s) {
        const uint32_t base = d0 + s * GSTG;
        const size_t oh = (size_t)c * 64;
        const size_t ol = 1536 + (size_t)c * 64;
        #pragma unroll
        for (int i = 0; i < 4; i++) {
            const size_t rs = (size_t)(32*i) * KC * 2;
            cpa16(base            + (32*i) * 80, Ap + oh + rs);
            cpa16(base + CSTG     + (32*i) * 80, Ap + ol + rs);
            cpa16(base + 2*CSTG   + (32*i) * 80, Bp + oh + rs);
            cpa16(base + 3*CSTG   + (32*i) * 80, Bp + ol + rs);
        }
        CP_COMMIT();
    };

    load_chunk(0, 0);

    for (int t = 0; t < NKI; t++) {
        CP_WAIT(0);
        __syncthreads();
        if (t + 1 < NKI) load_chunk(t + 1, (t + 1) & 1);

        const uint32_t sb = sm0 + (t & 1) * GSTG;
        #pragma unroll
        for (int ks = 0; ks < 2; ks++) {
            const uint32_t ko = ks * 32;
            uint32_t ah[4][4], al[4][4], bh[8][2], bl[8][2];
            #pragma unroll
            for (int mt = 0; mt < 4; mt++)
                ldsm4(ah[mt], sb + aOff + mt * (16 * 80) + ko);
            #pragma unroll
            for (int np = 0; np < 4; np++) {
                uint32_t tmp[4];
                ldsm4(tmp, sb + 2*CSTG + bOff + np * (16 * 80) + ko);
                bh[2*np][0] = tmp[0]; bh[2*np][1] = tmp[1];
                bh[2*np+1][0] = tmp[2]; bh[2*np+1][1] = tmp[3];
            }
            #pragma unroll
            for (int mt = 0; mt < 4; mt++)
                #pragma unroll
                for (int nt = 0; nt < 8; nt++)
                    mma16816(acc[mt][nt], ah[mt], bh[nt]);

            #pragma unroll
            for (int np = 0; np < 4; np++) {
                uint32_t tmp[4];
                ldsm4(tmp, sb + 3*CSTG + bOff + np * (16 * 80) + ko);
                bl[2*np][0] = tmp[0]; bl[2*np][1] = tmp[1];
                bl[2*np+1][0] = tmp[2]; bl[2*np+1][1] = tmp[3];
            }
            #pragma unroll
            for (int mt = 0; mt < 4; mt++)
                #pragma unroll
                for (int nt = 0; nt < 8; nt++)
                    mma16816(acc[mt][nt], ah[mt], bl[nt]);

            #pragma unroll
            for (int mt = 0; mt < 4; mt++)
                ldsm4(al[mt], sb + CSTG + aOff + mt * (16 * 80) + ko);
            #pragma unroll
            for (int mt = 0; mt < 4; mt++)
                #pragma unroll
                for (int nt = 0; nt < 8; nt++)
                    mma16816(acc[mt][nt], al[mt], bh[nt]);
        }
    }
}

// ---------------- QKV GEMM: epilogue writes attention-ready layouts ----------------
__global__ __launch_bounds__(128) void qkv_gemm_kernel()
{
    extern __shared__ char gsm[];
    const int n0 = blockIdx.x * 128;
    const int m0 = blockIdx.y * 128;

    float acc[4][8][4] = {};
    gemm_main(gxc, gw1c, m0, n0, acc, gsm);

    const int lane = threadIdx.x & 31, wid = threadIdx.x >> 5;
    const int wm = (wid & 1) * 64, wn = (wid >> 1) * 64;
    const int g = lane >> 2, tg = lane & 3;

    const int s3    = n0 / CDIM;
    const int nrem0 = n0 - s3 * CDIM;

    #pragma unroll
    for (int mt = 0; mt < 4; mt++) {
        #pragma unroll
        for (int nt = 0; nt < 8; nt++) {
            const int col = nrem0 + wn + nt * 8 + tg * 2;
            const int hh = col >> 6, e = col & 63;
            #pragma unroll
            for (int rr = 0; rr < 2; rr++) {
                const int mm = m0 + wm + mt * 16 + g + rr * 8;
                if (mm >= MROWS) continue;
                const int b = mm / NTOK;
                const int n = mm - b * NTOK;
                const size_t idx = (size_t)(b * H_ + hh) * NTOK + n;
                uint32_t hp, lp;
                pack_hilo(acc[mt][nt][rr * 2 + 0], acc[mt][nt][rr * 2 + 1], hp, lp);
                if (s3 == 0) {
                    *(uint32_t*)(g_qc + idx * 128 + e)      = hp;
                    *(uint32_t*)(g_qc + idx * 128 + 64 + e) = lp;
                } else if (s3 == 1) {
                    *(uint32_t*)(g_kc + idx * 128 + e)      = hp;
                    *(uint32_t*)(g_kc + idx * 128 + 64 + e) = lp;
                } else {
                    const __nv_bfloat162 h2 = *(__nv_bfloat162*)&hp;
                    const __nv_bfloat162 l2 = *(__nv_bfloat162*)&lp;
                    const size_t vi = ((size_t)(b * H_ + hh) * HD + e) * NTOK + n;
                    g_vht[vi]        = h2.x;
                    g_vht[vi + NTOK] = h2.y;
                    g_vlt[vi]        = l2.x;
                    g_vlt[vi + NTOK] = l2.y;
                }
            }
        }
    }
}

// ---------------- proj GEMM kernel ----------------
__global__ __launch_bounds__(128) void proj_gemm_kernel(const float* __restrict__ bias,
                                                        float* __restrict__ out)
{
    extern __shared__ char gsm[];
    const int n0 = blockIdx.x * 128;
    const int m0 = blockIdx.y * 128;

    float acc[4][8][4] = {};
    gemm_main(gaoc, gw2c, m0, n0, acc, gsm);

    const int lane = threadIdx.x & 31, wid = threadIdx.x >> 5;
    const int wm = (wid & 1) * 64, wn = (wid >> 1) * 64;
    const int g = lane >> 2, tg = lane & 3;

    #pragma unroll
    for (int mt = 0; mt < 4; mt++) {
        #pragma unroll
        for (int nt = 0; nt < 8; nt++) {
            const int d = n0 + wn + nt * 8 + tg * 2;
            const float b0 = bias[d], b1 = bias[d + 1];
            #pragma unroll
            for (int rr = 0; rr < 2; rr++) {
                const int m = m0 + wm + mt * 16 + g + rr * 8;
                if (m >= MROWS) continue;
                out[(size_t)m * CDIM + d]     = acc[mt][nt][rr * 2 + 0] + b0;
                out[(size_t)m * CDIM + d + 1] = acc[mt][nt][rr * 2 + 1] + b1;
            }
        }
    }
}

// ---------------- unified attention: mma flash kernel ----------------
// grid (9, 96): bx<8 image blocks (128 queries, 17 tiles); bx==8 text block
// (queries = tokens 0..127, first 40 stored, 1 tile, keylim TTXT).
// Double-buffered K and V; ONE barrier per tile; masking only on boundary tile.
#define QP     136
#define VPITCH 72
#define OFF_K  34816
#define KSTG   17408
#define OFF_VH (OFF_K + 2*KSTG)       // 69632
#define VSTG   9216
#define OFF_VL (OFF_VH + 2*VSTG)      // 88064
#define IMG_SMEM2 (OFF_VL + 2*VSTG)   // 106496
#define SMAX   20.0f

__global__ __launch_bounds__(128) void attn_mma_kernel()
{
    extern __shared__ char smx[];
    __nv_bfloat16* Qs = (__nv_bfloat16*)(smx);            // [128][136]

    const int bh = blockIdx.y;
    const bool istext = (blockIdx.x == 8);
    const int qtok   = istext ? 0 : TTXT + blockIdx.x * 128;
    const int ntiles = istext ? 1 : 17;
    const int keylim = istext ? TTXT : NTOK;

    const int tid = threadIdx.x;
    const int lane = tid & 31, wid = tid >> 5;
    const int g = lane >> 2, tg = lane & 3;
    const int wrow = wid * 32;

    const uint32_t qAddr  = (uint32_t)__cvta_generic_to_shared(Qs);
    const uint32_t ksAddr = (uint32_t)__cvta_generic_to_shared(smx + OFF_K);
    const uint32_t vhAddr = (uint32_t)__cvta_generic_to_shared(smx + OFF_VH);
    const uint32_t vlAddr = (uint32_t)__cvta_generic_to_shared(smx + OFF_VL);

    const uint32_t qBase = qAddr
        + ((wrow + (lane & 15)) * QP + (lane >> 4) * 8) * 2;
    const uint32_t kfragOff =
        ((((lane >> 4) * 8) + (lane & 7)) * QP + ((lane >> 3) & 1) * 8) * 2;
    const uint32_t vfragOff =
        ((((lane >> 4) * 8) + (lane & 7)) * VPITCH + ((lane >> 3) & 1) * 8) * 2;

    const __nv_bfloat16* qcb = g_qc + ((size_t)bh * NTOK + qtok) * 128;
    const __nv_bfloat16* kcb = g_kc + (size_t)bh * NTOK * 128;
    const __nv_bfloat16* vhb = g_vht + (size_t)bh * HD * NTOK;
    const __nv_bfloat16* vlb = g_vlt + (size_t)bh * HD * NTOK;

    auto load_k = [&](int jj, int stg) {
        const uint32_t kD = ksAddr + stg * KSTG;
        __nv_bfloat16* KsP = (__nv_bfloat16*)(smx + OFF_K + stg * KSTG);
        for (int u = tid; u < 64 * 16; u += 128) {
            int r = u >> 4, o = (u & 15) * 8;
            if (jj + r < NTOK)
                cpa16(kD + (r * QP + o) * 2, kcb + (size_t)(jj + r) * 128 + o);
            else
                *(uint4*)&KsP[r * QP + o] = make_uint4(0u, 0u, 0u, 0u);
        }
    };
    auto load_v = [&](int jj, int stg) {
        const uint32_t vhD = vhAddr + stg * VSTG;
        const uint32_t vlD = vlAddr + stg * VSTG;
        __nv_bfloat16* VhP = (__nv_bfloat16*)(smx + OFF_VH + stg * VSTG);
        __nv_bfloat16* VlP = (__nv_bfloat16*)(smx + OFF_VL + stg * VSTG);
        for (int u = tid; u < 64 * 8; u += 128) {
            int e = u >> 3, o = (u & 7) * 8;
            if (jj + o + 7 < NTOK) {
                cpa16(vhD + (e * VPITCH + o) * 2, vhb + (size_t)e * NTOK + jj + o);
                cpa16(vlD + (e * VPITCH + o) * 2, vlb + (size_t)e * NTOK + jj + o);
            } else {
                *(uint4*)&VhP[e * VPITCH + o] = make_uint4(0u, 0u, 0u, 0u);
                *(uint4*)&VlP[e * VPITCH + o] = make_uint4(0u, 0u, 0u, 0u);
            }
        }
    };

    // prologue: Q + K(0)/V(0) -> stage 0
    for (int u = tid; u < 128 * 16; u += 128) {
        int r = u >> 4, o = (u & 15) * 8;
        cpa16(qAddr + (r * QP + o) * 2, qcb + (size_t)r * 128 + o);
    }
    load_k(0, 0);
    load_v(0, 0);
    CP_COMMIT();

    float lsum[2][2] = {{0.f, 0.f}, {0.f, 0.f}};
    float O[2][8][4];
    #pragma unroll
    for (int mt = 0; mt < 2; mt++)
        #pragma unroll
        for (int nt = 0; nt < 8; nt++)
            #pragma unroll
            for (int j = 0; j < 4; j++) O[mt][nt][j] = 0.f;

    for (int t = 0; t < ntiles; t++) {
        const int j0 = t * 64;
        CP_WAIT(0);          // K(t), V(t) landed
        __syncthreads();     // also: all reads of stage (t-1)&1 finished

        // prefetch next tile into the other stages, overlapping ALL of tile t
        if (t + 1 < ntiles) {
            load_k(j0 + 64, (t + 1) & 1);
            load_v(j0 + 64, (t + 1) & 1);
            CP_COMMIT();
        }

        // ---- scores (K stage t&1) ----
        float S[2][8][4];
        #pragma unroll
        for (int mt = 0; mt < 2; mt++)
            #pragma unroll
            for (int nt = 0; nt < 8; nt++)
                #pragma unroll
                for (int j = 0; j < 4; j++) S[mt][nt][j] = 0.f;

        const uint32_t kBase = ksAddr + (t & 1) * KSTG + kfragOff;
        #pragma unroll
        for (int ks = 0; ks < 12; ks++) {
            const int qc = (ks < 8) ? (ks & 3) : (ks - 4);
            const int kc = (ks < 8) ? ks : (ks - 8);
            uint32_t a[2][4];
            ldsm4(a[0], qBase + qc * 32);
            ldsm4(a[1], qBase + 16 * (QP * 2) + qc * 32);
            uint32_t bfr[8][2];
            #pragma unroll
            for (int np = 0; np < 4; np++) {
                uint32_t tmp[4];
                ldsm4(tmp, kBase + np * (16 * QP * 2) + kc * 32);
                bfr[2*np][0]   = tmp[0];
                bfr[2*np][1]   = tmp[1];
                bfr[2*np+1][0] = tmp[2];
                bfr[2*np+1][1] = tmp[3];
            }
            #pragma unroll
            for (int nt = 0; nt < 8; nt++) {
                mma16816(S[0][nt], a[0], bfr[nt]);
                mma16816(S[1][nt], a[1], bfr[nt]);
            }
        }

        // ---- fixed-max softmax; mask only on the boundary tile ----
        if (j0 + 64 > keylim) {
            #pragma unroll
            for (int mt = 0; mt < 2; mt++)
                #pragma unroll
                for (int nt = 0; nt < 8; nt++) {
                    const int key = j0 + nt * 8 + tg * 2;
                    const bool v0 = key < keylim, v1 = key + 1 < keylim;
                    S[mt][nt][0] = v0 ? __expf(fmaf(S[mt][nt][0], 0.125f, -SMAX)) : 0.f;
                    S[mt][nt][1] = v1 ? __expf(fmaf(S[mt][nt][1], 0.125f, -SMAX)) : 0.f;
                    S[mt][nt][2] = v0 ? __expf(fmaf(S[mt][nt][2], 0.125f, -SMAX)) : 0.f;
                    S[mt][nt][3] = v1 ? __expf(fmaf(S[mt][nt][3], 0.125f, -SMAX)) : 0.f;
                    lsum[mt][0] += S[mt][nt][0] + S[mt][nt][1];
                    lsum[mt][1] += S[mt][nt][2] + S[mt][nt][3];
                }
        } else {
            #pragma unroll
            for (int mt = 0; mt < 2; mt++)
                #pragma unroll
                for (int nt = 0; nt < 8; nt++) {
                    S[mt][nt][0] = __expf(fmaf(S[mt][nt][0], 0.125f, -SMAX));
                    S[mt][nt][1] = __expf(fmaf(S[mt][nt][1], 0.125f, -SMAX));
                    S[mt][nt][2] = __expf(fmaf(S[mt][nt][2], 0.125f, -SMAX));
                    S[mt][nt][3] = __expf(fmaf(S[mt][nt][3], 0.125f, -SMAX));
                    lsum[mt][0] += S[mt][nt][0] + S[mt][nt][1];
                    lsum[mt][1] += S[mt][nt][2] + S[mt][nt][3];
                }
        }

        // pack P into A-fragments (hi + lo)
        uint32_t ph[2][4][4], pl[2][4][4];
        #pragma unroll
        for (int mt = 0; mt < 2; mt++) {
            #pragma unroll
            for (int ks = 0; ks < 4; ks++) {
                pack_hilo(S[mt][2*ks][0],   S[mt][2*ks][1],   ph[mt][ks][0], pl[mt][ks][0]);
                pack_hilo(S[mt][2*ks][2],   S[mt][2*ks][3],   ph[mt][ks][1], pl[mt][ks][1]);
                pack_hilo(S[mt][2*ks+1][0], S[mt][2*ks+1][1], ph[mt][ks][2], pl[mt][ks][2]);
                pack_hilo(S[mt][2*ks+1][2], S[mt][2*ks+1][3], ph[mt][ks][3], pl[mt][ks][3]);
            }
        }

        // ---- PV (V stage t&1) ----
        const uint32_t vhBase = vhAddr + (t & 1) * VSTG + vfragOff;
        const uint32_t vlBase = vlAddr + (t & 1) * VSTG + vfragOff;
        #pragma unroll
        for (int ks = 0; ks < 4; ks++) {
            uint32_t vh2[8][2], vl2[8][2];
            #pragma unroll
            for (int np = 0; np < 4; np++) {
                uint32_t th[4], tl[4];
                ldsm4(th, vhBase + np * (16 * VPITCH * 2) + ks * 32);
                ldsm4(tl, vlBase + np * (16 * VPITCH * 2) + ks * 32);
                vh2[2*np][0] = th[0]; vh2[2*np][1] = th[1];
                vh2[2*np+1][0] = th[2]; vh2[2*np+1][1] = th[3];
                vl2[2*np][0] = tl[0]; vl2[2*np][1] = tl[1];
                vl2[2*np+1][0] = tl[2]; vl2[2*np+1][1] = tl[3];
            }
            #pragma unroll
            for (int nt = 0; nt < 8; nt++) {
                #pragma unroll
                for (int mt = 0; mt < 2; mt++) {
                    mma16816(O[mt][nt], ph[mt][ks], vh2[nt]);
                    mma16816(O[mt][nt], ph[mt][ks], vl2[nt]);
                    mma16816(O[mt][nt], pl[mt][ks], vh2[nt]);
                }
            }
        }
    }

    // final row-sum reduction + epilogue (compact packed stores)
    const int b = bh / H_, h = bh - b * H_;
    #pragma unroll
    for (int mt = 0; mt < 2; mt++) {
        float r0 = lsum[mt][0], r1 = lsum[mt][1];
        r0 += __shfl_xor_sync(0xffffffffu, r0, 1);
        r0 += __shfl_xor_sync(0xffffffffu, r0, 2);
        r1 += __shfl_xor_sync(0xffffffffu, r1, 1);
        r1 += __shfl_xor_sync(0xffffffffu, r1, 2);
        const float inv0 = 1.f / r0, inv1 = 1.f / r1;
        const int rq0 = wrow + mt * 16 + g;
        const int rq1 = rq0 + 8;
        const int row0 = b * NTOK + qtok + rq0;
        const int row1 = row0 + 8;
        const bool st0 = !istext || (rq0 < TTXT);
        const bool st1 = !istext || (rq1 < TTXT);
        #pragma unroll
        for (int nt = 0; nt < 8; nt++) {
            const int c = h * HD + nt * 8 + tg * 2;
            uint32_t hp, lp;
            if (st0) {
                pack_hilo(O[mt][nt][0] * inv0, O[mt][nt][1] * inv0, hp, lp);
                *(uint32_t*)(gaoc + (size_t)row0 * KC + c)       = hp;
                *(uint32_t*)(gaoc + (size_t)row0 * KC + 768 + c) = lp;
            }
            if (st1) {
                pack_hilo(O[mt][nt][2] * inv1, O[mt][nt][3] * inv1, hp, lp);
                *(uint32_t*)(gaoc + (size_t)row1 * KC + c)       = hp;
                *(uint32_t*)(gaoc + (size_t)row1 * KC + 768 + c) = lp;
            }
        }
    }
}

// ---------------- launch ----------------
extern "C" void kernel_launch(void* const* d_in, const int* in_sizes, int n_in,
                              void* d_out, int out_size)
{
    const float* x      = (const float*)d_in[0];
    const float* qkv_w  = (const float*)d_in[1];
    const float* proj_w = (const float*)d_in[2];
    const float* proj_b = (const float*)d_in[3];
    float* out = (float*)d_out;

    cudaFuncSetAttribute(attn_mma_kernel,
                         cudaFuncAttributeMaxDynamicSharedMemorySize, IMG_SMEM2);
    cudaFuncSetAttribute(qkv_gemm_kernel,
                         cudaFuncAttributeMaxDynamicSharedMemorySize, GEMM_SMEM);
    cudaFuncSetAttribute(proj_gemm_kernel,
                         cudaFuncAttributeMaxDynamicSharedMemorySize, GEMM_SMEM);

    split_x_kernel<<<(MPAD*(CDIM/2) + 255)/256, 256>>>(x);
    split_w_kernel<<<((NQKV+CDIM)*(CDIM/2) + 255)/256, 256>>>(qkv_w, proj_w);

    qkv_gemm_kernel<<<dim3(NQKV/128, MPAD/128), 128, GEMM_SMEM>>>();

    attn_mma_kernel<<<dim3(9, B_*H_), 128, IMG_SMEM2>>>();

    proj_gemm_kernel<<<dim3(CDIM/128, MPAD/128), 128, GEMM_SMEM>>>(proj_b, out);
}